// round 17
// baseline (speedup 1.0000x reference)
#include <cuda_runtime.h>

// MAE_52613349376068: mean(2 - 2*softmax(outputs)[i, targets[i]])
// outputs: [131072, 1000] fp32, targets: [131072] int32, out: scalar fp32.
//
// Single fused kernel; cross-CTA reduction via ONE relaxed 64-bit atomicAdd
// packing {count[50:64) | fixed-point sum[0:50)}. Exact integer adds ->
// deterministic, no fences (gpu-scope ordering per CTA cost ~8us, R11/R13).
//
// R17 change: __launch_bounds__(256, 6) raises the register budget 32 -> 42
// so all 8 front-batched LDG.128 results stay live simultaneously (at 32
// regs ptxas must split the batch -> true MLP ~4-5). 6 CTAs/SM x 8 warps x
// 8 lines = 384 outstanding lines/SM, deeper than the 8-CTA/32-reg config.
// Row loads use __ldcs (evict-first): data is single-touch streaming.

static constexpr int B = 131072;
static constexpr int C = 1000;
static constexpr int ROWS_PER_CTA = 8;        // 8 warps = 256 threads
static constexpr int NBLK = B / ROWS_PER_CTA; // 16384 CTAs

static constexpr unsigned long long CNT_ONE = 1ull << 50;
static constexpr unsigned long long VAL_MASK = CNT_ONE - 1ull;
static constexpr float FIX_SCALE = 2147483648.0f;  // 2^31

__device__ unsigned long long g_acc;          // zero-initialized

__global__ __launch_bounds__(256, 6) void mae_fused_kernel(
    const float* __restrict__ x,
    const int* __restrict__ tgt,
    float* __restrict__ out)
{
    const int warp = threadIdx.x >> 5;
    const int lane = threadIdx.x & 31;
    const int row = blockIdx.x * ROWS_PER_CTA + warp;

    const float* xr = x + (long long)row * C;
    const float4* rp = reinterpret_cast<const float4*>(xr);

    // Prefetch target logit (broadcast); issued first, consumed last.
    const int t = tgt[row];
    const float xt = __ldg(xr + t);

    // 8 front-batched LDG.128 (streaming, evict-first), no branches.
    // Lanes 26..31 of the 8th load read a valid in-row duplicate index
    // (lane+192 < 250; dedup'd in L1) and are masked below.
    const float tmask = (lane < 26) ? 1.0f : 0.0f;
    const int tidx = (lane < 26) ? (lane + 224) : (lane + 192);

    float4 v[7];
    #pragma unroll
    for (int k = 0; k < 7; k++) v[k] = __ldcs(rp + lane + 32 * k);
    float4 w = __ldcs(rp + tidx);

    float s = 0.0f;
    #pragma unroll
    for (int k = 0; k < 7; k++) {
        s += (__expf(v[k].x) + __expf(v[k].y))
           + (__expf(v[k].z) + __expf(v[k].w));
    }
    s += tmask * ((__expf(w.x) + __expf(w.y)) + (__expf(w.z) + __expf(w.w)));

    // Warp reduce sum.
    #pragma unroll
    for (int off = 16; off; off >>= 1)
        s += __shfl_xor_sync(0xFFFFFFFFu, s, off);

    __shared__ float sh[ROWS_PER_CTA];
    if (lane == 0) {
        float p = __expf(xt) / s;
        sh[warp] = 2.0f - 2.0f * p;   // in [0, 2)
    }
    __syncthreads();

    if (threadIdx.x == 0) {
        float acc = 0.0f;
        #pragma unroll
        for (int i = 0; i < ROWS_PER_CTA; i++) acc += sh[i];

        // Fixed-point contribution + count bump in ONE relaxed atomic.
        const unsigned long long val = __float2ull_rn(acc * FIX_SCALE);
        unsigned long long old = atomicAdd(&g_acc, CNT_ONE + val);

        if ((old >> 50) == (unsigned long long)(NBLK - 1)) {
            unsigned long long total = (old & VAL_MASK) + val;
            out[0] = (float)((double)total *
                             (1.0 / ((double)FIX_SCALE * (double)B)));
            g_acc = 0ull;  // reset for next graph replay
        }
    }
}

extern "C" void kernel_launch(void* const* d_in, const int* in_sizes, int n_in,
                              void* d_out, int out_size)
{
    const float* x = (const float*)d_in[0];
    const int* tgt = (const int*)d_in[1];
    float* out = (float*)d_out;

    mae_fused_kernel<<<NBLK, 256>>>(x, tgt, out);
}